// round 7
// baseline (speedup 1.0000x reference)
#include <cuda_runtime.h>
#include <cuda_bf16.h>
#include <math.h>
#include <stdint.h>

#define NN    100000
#define EE    1600000
#define HIDD  128
#define BB    512
#define LLAY  3
#define EPSV  1e-5f
#define NPART ((NN + 1023) / 1024)

// ---------------- scratch (device globals; allocation-free) ----------------
__device__ __align__(16) float g_x  [NN * HIDD];   // fp32 activations
__device__ __align__(16) float g_xw [NN * HIDD];   // GEMM output (fp32)
__device__ __align__(16) __nv_bfloat16 g_xh[NN * HIDD];  // A hi split for GEMM
__device__ __align__(16) __nv_bfloat16 g_xl[NN * HIDD];  // A lo split
__device__ __align__(16) __nv_bfloat16 g_wh[4 * HIDD * HIDD];
__device__ __align__(16) __nv_bfloat16 g_wl[4 * HIDD * HIDD];
__device__ __align__(16) float g_dinv [NN];
__device__ __align__(16) float g_dinvs[NN];
__device__ __align__(16) float g_pool[BB * HIDD];
__device__ __align__(16) float g_cnt [BB];
// CSR
__device__ int   g_ecnt[NN];
__device__ int   g_cur [NN];
__device__ int   g_scan[NN];
__device__ int   g_rows[NN];
__device__ int   g_part [NPART];
__device__ int   g_partS[NPART];
__device__ int   g_csr_src[EE];
__device__ float g_csr_w  [EE];

// ---------------- helpers ----------------
__device__ __forceinline__ void red_add_v4(float* p, float4 v) {
    asm volatile("red.global.add.v4.f32 [%0], {%1, %2, %3, %4};"
                 :: "l"(p), "f"(v.x), "f"(v.y), "f"(v.z), "f"(v.w)
                 : "memory");
}
__device__ __forceinline__ uint32_t smem_u32(const void* p) {
    uint32_t a;
    asm("{ .reg .u64 t; cvta.to.shared.u64 t, %1; cvt.u32.u64 %0, t; }"
        : "=r"(a) : "l"(p));
    return a;
}
__device__ __forceinline__ void cp16(uint32_t smaddr, const void* g) {
    asm volatile("cp.async.cg.shared.global [%0], [%1], 16;"
                 :: "r"(smaddr), "l"(g) : "memory");
}
__device__ __forceinline__ void cp_commit_wait() {
    asm volatile("cp.async.commit_group;" ::: "memory");
    asm volatile("cp.async.wait_group 0;" ::: "memory");
}
__device__ __forceinline__ void ldm_x4(uint32_t* r, uint32_t addr) {
    asm volatile("ldmatrix.sync.aligned.m8n8.x4.shared.b16 {%0,%1,%2,%3}, [%4];"
                 : "=r"(r[0]), "=r"(r[1]), "=r"(r[2]), "=r"(r[3]) : "r"(addr));
}
__device__ __forceinline__ void ldm_x4_t(uint32_t* r, uint32_t addr) {
    asm volatile("ldmatrix.sync.aligned.m8n8.x4.trans.shared.b16 {%0,%1,%2,%3}, [%4];"
                 : "=r"(r[0]), "=r"(r[1]), "=r"(r[2]), "=r"(r[3]) : "r"(addr));
}
__device__ __forceinline__ void mma_bf16(float* c, const uint32_t* a,
                                         uint32_t b0, uint32_t b1) {
    asm volatile(
        "mma.sync.aligned.m16n8k16.row.col.f32.bf16.bf16.f32 "
        "{%0,%1,%2,%3}, {%4,%5,%6,%7}, {%8,%9}, {%0,%1,%2,%3};"
        : "+f"(c[0]), "+f"(c[1]), "+f"(c[2]), "+f"(c[3])
        : "r"(a[0]), "r"(a[1]), "r"(a[2]), "r"(a[3]), "r"(b0), "r"(b1));
}
__device__ __forceinline__ uint32_t pack_bf16x2(float a, float b) {
    __nv_bfloat162 h2 = __float22bfloat162_rn(make_float2(a, b));
    return *reinterpret_cast<uint32_t*>(&h2);
}

// ---------------- init (covers all of NN — graph-replay determinism) --------
__global__ void k_init() {
    int i = blockIdx.x * blockDim.x + threadIdx.x;
    if (i < NN)        { g_ecnt[i] = 0; g_cur[i] = 0; }
    if (i < BB * HIDD) g_pool[i] = 0.0f;
    if (i < BB)        g_cnt[i]  = 0.0f;
}

// ---------------- pre-split all weight matrices to bf16 hi/lo ---------------
__global__ void k_wconv(const float* __restrict__ w_in,
                        const float* __restrict__ gcn_w) {
    int i = blockIdx.x * blockDim.x + threadIdx.x;
    if (i >= 4 * HIDD * HIDD) return;
    float v = (i < HIDD * HIDD) ? w_in[i] : gcn_w[i - HIDD * HIDD];
    __nv_bfloat16 h = __float2bfloat16(v);
    g_wh[i] = h;
    g_wl[i] = __float2bfloat16(v - __bfloat162float(h));
}

__global__ void k_deg(const int* __restrict__ dst) {
    int e = blockIdx.x * blockDim.x + threadIdx.x;
    if (e < EE) atomicAdd(&g_ecnt[dst[e]], 1);
}

// ---------------- scan / CSR build ----------------
__global__ void k_scan_blk() {
    __shared__ int sm[1024];
    int i = blockIdx.x * 1024 + threadIdx.x;
    int v = (i < NN) ? g_ecnt[i] : 0;
    sm[threadIdx.x] = v;
    __syncthreads();
    #pragma unroll
    for (int off = 1; off < 1024; off <<= 1) {
        int t = (threadIdx.x >= off) ? sm[threadIdx.x - off] : 0;
        __syncthreads();
        sm[threadIdx.x] += t;
        __syncthreads();
    }
    if (i < NN) g_scan[i] = sm[threadIdx.x];
    if (threadIdx.x == 1023) g_part[blockIdx.x] = sm[1023];
}

__global__ void k_scan_top() {
    if (threadIdx.x == 0) {
        int s = 0;
        for (int b = 0; b < NPART; b++) { s += g_part[b]; g_partS[b] = s; }
    }
}

// fused: row offsets + degree norms
__global__ void k_scan_fin() {
    int i = blockIdx.x * blockDim.x + threadIdx.x;
    if (i >= NN) return;
    int b = i >> 10;
    int cnt = g_ecnt[i];
    g_rows[i] = g_scan[i] - cnt + (b ? g_partS[b - 1] : 0);
    float d = (float)cnt + 1.0f;
    g_dinv[i]  = 1.0f / d;
    g_dinvs[i] = rsqrtf(d);
}

__global__ void k_fill(const int* __restrict__ src, const int* __restrict__ dst) {
    int e = blockIdx.x * blockDim.x + threadIdx.x;
    if (e >= EE) return;
    int s = src[e], d = dst[e];
    int slot = g_rows[d] + atomicAdd(&g_cur[d], 1);
    g_csr_src[slot] = s;
    g_csr_w[slot]   = g_dinvs[s] * g_dinvs[d];
}

// ======== GEMM: [M,128] @ [128,128], 3-pass split-bf16 mma.sync =============
// mode 0: A from fp32 nodes (convert in kernel); out = bf16 splits (+bias)
// mode 1: A from pre-split g_xh/g_xl via cp.async;  out = g_xw fp32
// W selected by wslot INSIDE the kernel (device symbols can't cross host).
#define GSTRIDE 272
#define GTILE   (128 * GSTRIDE)
#define OFF_AHI 0
#define OFF_ALO (GTILE)
#define OFF_WHI (2 * GTILE)
#define OFF_WLO (3 * GTILE)
#define GSMEM   (4 * GTILE)              // 139264 B

__global__ void __launch_bounds__(256, 1)
k_gemm_mma(const float* __restrict__ Xf32,
           const float* __restrict__ bias,
           int M, int mode, int wslot)
{
    extern __shared__ char smem[];
    const uint32_t smb = smem_u32(smem);
    const int tid  = threadIdx.x;
    const int row0 = blockIdx.x * 128;

    const __nv_bfloat16* Wh = g_wh + wslot * HIDD * HIDD;
    const __nv_bfloat16* Wl = g_wl + wslot * HIDD * HIDD;

    // ---- W tiles via cp.async (bf16, pre-split) ----
    #pragma unroll
    for (int t = 0; t < 8; t++) {
        int idx = tid + 256 * t;          // 0..2047
        int row = idx >> 4;
        int c   = idx & 15;
        uint32_t so = row * GSTRIDE + c * 16;
        int ge = row * 128 + c * 8;
        cp16(smb + OFF_WHI + so, Wh + ge);
        cp16(smb + OFF_WLO + so, Wl + ge);
    }

    if (mode == 0) {
        // A from fp32, convert + split in kernel
        const float2* X2 = reinterpret_cast<const float2*>(Xf32);
        #pragma unroll
        for (int i = 0; i < 32; i++) {
            int idx = tid + 256 * i;
            int row = idx >> 6;
            int kp  = idx & 63;
            int gr  = row0 + row;
            float2 v = (gr < M) ? X2[gr * 64 + kp] : make_float2(0.f, 0.f);
            __nv_bfloat162 h2 = __float22bfloat162_rn(v);
            float2 hf = __bfloat1622float2(h2);
            __nv_bfloat162 l2 = __float22bfloat162_rn(
                                   make_float2(v.x - hf.x, v.y - hf.y));
            int off = row * GSTRIDE + kp * 4;
            *reinterpret_cast<uint32_t*>(smem + OFF_AHI + off) =
                *reinterpret_cast<uint32_t*>(&h2);
            *reinterpret_cast<uint32_t*>(smem + OFF_ALO + off) =
                *reinterpret_cast<uint32_t*>(&l2);
        }
    } else {
        // A from pre-split bf16 via cp.async; zero-fill OOB rows
        const uint4 z4 = make_uint4(0, 0, 0, 0);
        #pragma unroll
        for (int t = 0; t < 8; t++) {
            int idx = tid + 256 * t;
            int row = idx >> 4;
            int c   = idx & 15;
            uint32_t so = row * GSTRIDE + c * 16;
            int gr = row0 + row;
            if (gr < M) {
                int ge = gr * 128 + c * 8;
                cp16(smb + OFF_AHI + so, g_xh + ge);
                cp16(smb + OFF_ALO + so, g_xl + ge);
            } else {
                *reinterpret_cast<uint4*>(smem + OFF_AHI + so) = z4;
                *reinterpret_cast<uint4*>(smem + OFF_ALO + so) = z4;
            }
        }
    }
    cp_commit_wait();
    __syncthreads();

    const int wid  = tid >> 5;
    const int lane = tid & 31;
    const int mb   = (wid >> 1) * 32;
    const int nb   = (wid & 1) * 64;

    const int a_r  = lane & 15;
    const int a_kb = (lane >> 4) << 4;
    const int b_r  = lane & 7;
    const int b_kh = ((lane >> 3) & 1) << 3;
    const int b_nh = ((lane >> 4) & 1) << 3;

    float acc[2][8][4];
    #pragma unroll
    for (int mt = 0; mt < 2; mt++)
        #pragma unroll
        for (int nt = 0; nt < 8; nt++)
            #pragma unroll
            for (int q = 0; q < 4; q++) acc[mt][nt][q] = 0.f;

    const uint32_t passA[3] = {OFF_AHI, OFF_AHI, OFF_ALO};
    const uint32_t passB[3] = {OFF_WHI, OFF_WLO, OFF_WHI};

    #pragma unroll
    for (int p = 0; p < 3; p++) {
        uint32_t Ab = smb + passA[p];
        uint32_t Bb = smb + passB[p];
        #pragma unroll
        for (int ks = 0; ks < 8; ks++) {
            uint32_t a[2][4];
            ldm_x4(a[0], Ab + (mb + a_r) * GSTRIDE + ks * 32 + a_kb);
            ldm_x4(a[1], Ab + (mb + 16 + a_r) * GSTRIDE + ks * 32 + a_kb);
            #pragma unroll
            for (int np = 0; np < 4; np++) {
                uint32_t b[4];
                ldm_x4_t(b, Bb + (ks * 16 + b_kh + b_r) * GSTRIDE
                             + (nb + np * 16 + b_nh) * 2);
                mma_bf16(acc[0][np*2],   a[0], b[0], b[1]);
                mma_bf16(acc[0][np*2+1], a[0], b[2], b[3]);
                mma_bf16(acc[1][np*2],   a[1], b[0], b[1]);
                mma_bf16(acc[1][np*2+1], a[1], b[2], b[3]);
            }
        }
    }

    // ---- epilogue ----
    const int tq = lane >> 2;
    const int tr = (lane & 3) * 2;
    #pragma unroll
    for (int mt = 0; mt < 2; mt++) {
        int rbase = row0 + mb + mt * 16 + tq;
        #pragma unroll
        for (int nt = 0; nt < 8; nt++) {
            int col = nb + nt * 8 + tr;
            float2 v0 = make_float2(acc[mt][nt][0], acc[mt][nt][1]);
            float2 v1 = make_float2(acc[mt][nt][2], acc[mt][nt][3]);
            if (mode == 0) {
                float2 bv = *reinterpret_cast<const float2*>(&bias[col]);
                v0.x += bv.x; v0.y += bv.y;
                v1.x += bv.x; v1.y += bv.y;
                // write bf16 splits only (consumed by layer-0 GEMM)
                if (rbase < M) {
                    float hx = __bfloat162float(__float2bfloat16(v0.x));
                    float hy = __bfloat162float(__float2bfloat16(v0.y));
                    *reinterpret_cast<uint32_t*>(&g_xh[rbase * 128 + col]) =
                        pack_bf16x2(v0.x, v0.y);
                    *reinterpret_cast<uint32_t*>(&g_xl[rbase * 128 + col]) =
                        pack_bf16x2(v0.x - hx, v0.y - hy);
                }
                if (rbase + 8 < M) {
                    float hx = __bfloat162float(__float2bfloat16(v1.x));
                    float hy = __bfloat162float(__float2bfloat16(v1.y));
                    *reinterpret_cast<uint32_t*>(&g_xh[(rbase + 8) * 128 + col]) =
                        pack_bf16x2(v1.x, v1.y);
                    *reinterpret_cast<uint32_t*>(&g_xl[(rbase + 8) * 128 + col]) =
                        pack_bf16x2(v1.x - hx, v1.y - hy);
                }
            } else {
                if (rbase < M)
                    *reinterpret_cast<float2*>(&g_xw[rbase * 128 + col]) = v0;
                if (rbase + 8 < M)
                    *reinterpret_cast<float2*>(&g_xw[(rbase + 8) * 128 + col]) = v1;
            }
        }
    }
}

// ------- fused: CSR gather-aggregate + self-loop + bias + LN + ReLU + res ---
__global__ void k_aggln(const float* __restrict__ bias,
                        const float* __restrict__ gamma,
                        const float* __restrict__ beta,
                        float* __restrict__ dout,
                        int add_res, int write_out, int write_splits)
{
    int t = blockIdx.x * blockDim.x + threadIdx.x;
    int n    = t >> 5;
    int lane = t & 31;
    if (n >= NN) return;

    const float4* xw4 = reinterpret_cast<const float4*>(g_xw);

    float di  = g_dinv[n];
    float4 sv = xw4[n * 32 + lane];
    float4 acc = make_float4(sv.x * di, sv.y * di, sv.z * di, sv.w * di);

    int beg = g_rows[n];
    int end = beg + g_ecnt[n];
    int k = beg;
    for (; k + 4 <= end; k += 4) {
        int   s0 = g_csr_src[k],   s1 = g_csr_src[k+1];
        int   s2 = g_csr_src[k+2], s3 = g_csr_src[k+3];
        float w0 = g_csr_w[k],   w1 = g_csr_w[k+1];
        float w2 = g_csr_w[k+2], w3 = g_csr_w[k+3];
        float4 v0 = xw4[s0 * 32 + lane];
        float4 v1 = xw4[s1 * 32 + lane];
        float4 v2 = xw4[s2 * 32 + lane];
        float4 v3 = xw4[s3 * 32 + lane];
        acc.x = fmaf(v0.x, w0, fmaf(v1.x, w1, fmaf(v2.x, w2, fmaf(v3.x, w3, acc.x))));
        acc.y = fmaf(v0.y, w0, fmaf(v1.y, w1, fmaf(v2.y, w2, fmaf(v3.y, w3, acc.y))));
        acc.z = fmaf(v0.z, w0, fmaf(v1.z, w1, fmaf(v2.z, w2, fmaf(v3.z, w3, acc.z))));
        acc.w = fmaf(v0.w, w0, fmaf(v1.w, w1, fmaf(v2.w, w2, fmaf(v3.w, w3, acc.w))));
    }
    for (; k < end; k++) {
        int s = g_csr_src[k];
        float w = g_csr_w[k];
        float4 v = xw4[s * 32 + lane];
        acc.x = fmaf(v.x, w, acc.x);
        acc.y = fmaf(v.y, w, acc.y);
        acc.z = fmaf(v.z, w, acc.z);
        acc.w = fmaf(v.w, w, acc.w);
    }

    float4 bv = reinterpret_cast<const float4*>(bias)[lane];
    acc.x += bv.x; acc.y += bv.y; acc.z += bv.z; acc.w += bv.w;

    float s = acc.x + acc.y + acc.z + acc.w;
    float q = acc.x*acc.x + acc.y*acc.y + acc.z*acc.z + acc.w*acc.w;
    #pragma unroll
    for (int o = 16; o; o >>= 1) {
        s += __shfl_xor_sync(0xffffffffu, s, o);
        q += __shfl_xor_sync(0xffffffffu, q, o);
    }
    float mu  = s * (1.0f / 128.0f);
    float var = q * (1.0f / 128.0f) - mu * mu;
    float rs  = rsqrtf(var + EPSV);

    float4 gg = reinterpret_cast<const float4*>(gamma)[lane];
    float4 bt = reinterpret_cast<const float4*>(beta)[lane];
    float4 y;
    y.x = fmaxf(fmaf((acc.x - mu) * rs, gg.x, bt.x), 0.f);
    y.y = fmaxf(fmaf((acc.y - mu) * rs, gg.y, bt.y), 0.f);
    y.z = fmaxf(fmaf((acc.z - mu) * rs, gg.z, bt.z), 0.f);
    y.w = fmaxf(fmaf((acc.w - mu) * rs, gg.w, bt.w), 0.f);

    if (add_res) {
        float4 r = reinterpret_cast<const float4*>(g_x)[n * 32 + lane];
        y.x += r.x; y.y += r.y; y.z += r.z; y.w += r.w;
    }
    reinterpret_cast<float4*>(g_x)[n * 32 + lane] = y;
    if (write_out)
        reinterpret_cast<float4*>(dout)[n * 32 + lane] = y;

    if (write_splits) {
        float hx = __bfloat162float(__float2bfloat16(y.x));
        float hy = __bfloat162float(__float2bfloat16(y.y));
        float hz = __bfloat162float(__float2bfloat16(y.z));
        float hw = __bfloat162float(__float2bfloat16(y.w));
        uint2 hv, lv;
        hv.x = pack_bf16x2(y.x, y.y);
        hv.y = pack_bf16x2(y.z, y.w);
        lv.x = pack_bf16x2(y.x - hx, y.y - hy);
        lv.y = pack_bf16x2(y.z - hz, y.w - hw);
        *reinterpret_cast<uint2*>(&g_xh[n * 128 + lane * 4]) = hv;
        *reinterpret_cast<uint2*>(&g_xl[n * 128 + lane * 4]) = lv;
    }
}

// ---------------- global mean pool ------------------------------------------
__global__ void k_pool(const int* __restrict__ batch_idx) {
    int t = blockIdx.x * blockDim.x + threadIdx.x;
    int n = t >> 5;
    int j = t & 31;
    if (n >= NN) return;
    int b = batch_idx[n];
    float4 v = reinterpret_cast<const float4*>(g_x)[n * 32 + j];
    red_add_v4(&g_pool[b * 128 + j * 4], v);
    if (j == 0) atomicAdd(&g_cnt[b], 1.0f);
}

__global__ void k_poolfin(float* __restrict__ dout) {
    int i = blockIdx.x * blockDim.x + threadIdx.x;
    if (i >= BB * HIDD) return;
    int b = i >> 7;
    dout[NN * HIDD + i] = g_pool[i] / fmaxf(g_cnt[b], 1.0f);
}

// ---------------- launch ------------------------------------------------------
extern "C" void kernel_launch(void* const* d_in, const int* in_sizes, int n_in,
                              void* d_out, int out_size)
{
    const float* nodes     = (const float*)d_in[0];
    const int*   edges     = (const int*)  d_in[1];
    const int*   batch_idx = (const int*)  d_in[3];
    const float* w_in      = (const float*)d_in[4];
    const float* b_in      = (const float*)d_in[5];
    const float* gcn_w     = (const float*)d_in[6];
    const float* gcn_b     = (const float*)d_in[7];
    const float* ln_g      = (const float*)d_in[8];
    const float* ln_b      = (const float*)d_in[9];
    float*       out       = (float*)d_out;

    const int* src = edges;
    const int* dst = edges + EE;

    cudaFuncSetAttribute(k_gemm_mma, cudaFuncAttributeMaxDynamicSharedMemorySize, GSMEM);

    const int T = 256;
    const int INIT_N = (NN > BB * HIDD) ? NN : (BB * HIDD);
    k_init <<<(INIT_N + T - 1) / T, T>>>();
    k_wconv<<<(4 * HIDD * HIDD + T - 1) / T, T>>>(w_in, gcn_w);
    k_deg  <<<(EE + T - 1) / T, T>>>(dst);

    k_scan_blk<<<NPART, 1024>>>();
    k_scan_top<<<1, 32>>>();
    k_scan_fin<<<(NN + T - 1) / T, T>>>();
    k_fill<<<(EE + T - 1) / T, T>>>(src, dst);

    const int GEMM_GRID = (NN + 127) / 128;
    // input projection: A from fp32 nodes, W slot 0
    k_gemm_mma<<<GEMM_GRID, T, GSMEM>>>(nodes, b_in, NN, 0, 0);

    for (int i = 0; i < LLAY; i++) {
        k_gemm_mma<<<GEMM_GRID, T, GSMEM>>>(nullptr, nullptr, NN, 1, i + 1);
        k_aggln<<<(NN * 32 + T - 1) / T, T>>>(gcn_b + i * HIDD,
                                              ln_g + i * HIDD, ln_b + i * HIDD,
                                              out, (i > 0) ? 1 : 0,
                                              (i == LLAY - 1) ? 1 : 0,
                                              (i < LLAY - 1) ? 1 : 0);
    }

    k_pool   <<<(NN * 32 + T - 1) / T, T>>>(batch_idx);
    k_poolfin<<<(BB * HIDD + T - 1) / T, T>>>(out);
}

// round 8
// speedup vs baseline: 1.0362x; 1.0362x over previous
#include <cuda_runtime.h>
#include <cuda_bf16.h>
#include <math.h>
#include <stdint.h>

#define NN    100000
#define EE    1600000
#define HIDD  128
#define BB    512
#define LLAY  3
#define EPSV  1e-5f
#define NPART ((NN + 1023) / 1024)

// ---------------- scratch (device globals; allocation-free) ----------------
__device__ __align__(16) float g_x  [NN * HIDD];
__device__ __align__(16) float g_xw [NN * HIDD];
__device__ __align__(16) __nv_bfloat16 g_wh[4 * HIDD * HIDD];
__device__ __align__(16) __nv_bfloat16 g_wl[4 * HIDD * HIDD];
__device__ __align__(16) float g_dinv [NN];
__device__ __align__(16) float g_dinvs[NN];
__device__ __align__(16) float g_pool[BB * HIDD];
__device__ __align__(16) float g_cnt [BB];
// CSR
__device__ int   g_ecnt[NN];
__device__ int   g_cur [NN];
__device__ int   g_scan[NN];
__device__ int   g_rows[NN];
__device__ int   g_part [NPART];
__device__ int   g_partS[NPART];
__device__ int   g_csr_src[EE];
__device__ float g_csr_w  [EE];

// ---------------- helpers ----------------
__device__ __forceinline__ void red_add_v4(float* p, float4 v) {
    asm volatile("red.global.add.v4.f32 [%0], {%1, %2, %3, %4};"
                 :: "l"(p), "f"(v.x), "f"(v.y), "f"(v.z), "f"(v.w)
                 : "memory");
}
__device__ __forceinline__ uint32_t smem_u32(const void* p) {
    uint32_t a;
    asm("{ .reg .u64 t; cvta.to.shared.u64 t, %1; cvt.u32.u64 %0, t; }"
        : "=r"(a) : "l"(p));
    return a;
}
__device__ __forceinline__ void cp16(uint32_t smaddr, const void* g) {
    asm volatile("cp.async.cg.shared.global [%0], [%1], 16;"
                 :: "r"(smaddr), "l"(g) : "memory");
}
__device__ __forceinline__ void cp_commit_wait() {
    asm volatile("cp.async.commit_group;" ::: "memory");
    asm volatile("cp.async.wait_group 0;" ::: "memory");
}
__device__ __forceinline__ void ldm_x4(uint32_t* r, uint32_t addr) {
    asm volatile("ldmatrix.sync.aligned.m8n8.x4.shared.b16 {%0,%1,%2,%3}, [%4];"
                 : "=r"(r[0]), "=r"(r[1]), "=r"(r[2]), "=r"(r[3]) : "r"(addr));
}
__device__ __forceinline__ void ldm_x4_t(uint32_t* r, uint32_t addr) {
    asm volatile("ldmatrix.sync.aligned.m8n8.x4.trans.shared.b16 {%0,%1,%2,%3}, [%4];"
                 : "=r"(r[0]), "=r"(r[1]), "=r"(r[2]), "=r"(r[3]) : "r"(addr));
}
__device__ __forceinline__ void mma_bf16(float* c, const uint32_t* a,
                                         uint32_t b0, uint32_t b1) {
    asm volatile(
        "mma.sync.aligned.m16n8k16.row.col.f32.bf16.bf16.f32 "
        "{%0,%1,%2,%3}, {%4,%5,%6,%7}, {%8,%9}, {%0,%1,%2,%3};"
        : "+f"(c[0]), "+f"(c[1]), "+f"(c[2]), "+f"(c[3])
        : "r"(a[0]), "r"(a[1]), "r"(a[2]), "r"(a[3]), "r"(b0), "r"(b1));
}

// ---------------- init (covers all of NN — graph-replay determinism) --------
__global__ void k_init() {
    int i = blockIdx.x * blockDim.x + threadIdx.x;
    if (i < NN)        { g_ecnt[i] = 0; g_cur[i] = 0; }
    if (i < BB * HIDD) g_pool[i] = 0.0f;
    if (i < BB)        g_cnt[i]  = 0.0f;
}

// ---------------- pre-split all weight matrices to bf16 hi/lo ---------------
__global__ void k_wconv(const float* __restrict__ w_in,
                        const float* __restrict__ gcn_w) {
    int i = blockIdx.x * blockDim.x + threadIdx.x;
    if (i >= 4 * HIDD * HIDD) return;
    float v = (i < HIDD * HIDD) ? w_in[i] : gcn_w[i - HIDD * HIDD];
    __nv_bfloat16 h = __float2bfloat16(v);
    g_wh[i] = h;
    g_wl[i] = __float2bfloat16(v - __bfloat162float(h));
}

__global__ void k_deg(const int* __restrict__ dst) {
    int e = blockIdx.x * blockDim.x + threadIdx.x;
    if (e < EE) atomicAdd(&g_ecnt[dst[e]], 1);
}

// ---------------- scan / CSR build ----------------
__global__ void k_scan_blk() {
    __shared__ int sm[1024];
    int i = blockIdx.x * 1024 + threadIdx.x;
    int v = (i < NN) ? g_ecnt[i] : 0;
    sm[threadIdx.x] = v;
    __syncthreads();
    #pragma unroll
    for (int off = 1; off < 1024; off <<= 1) {
        int t = (threadIdx.x >= off) ? sm[threadIdx.x - off] : 0;
        __syncthreads();
        sm[threadIdx.x] += t;
        __syncthreads();
    }
    if (i < NN) g_scan[i] = sm[threadIdx.x];
    if (threadIdx.x == 1023) g_part[blockIdx.x] = sm[1023];
}

__global__ void k_scan_top() {
    if (threadIdx.x == 0) {
        int s = 0;
        for (int b = 0; b < NPART; b++) { s += g_part[b]; g_partS[b] = s; }
    }
}

// fused: row offsets + degree norms
__global__ void k_scan_fin() {
    int i = blockIdx.x * blockDim.x + threadIdx.x;
    if (i >= NN) return;
    int b = i >> 10;
    int cnt = g_ecnt[i];
    g_rows[i] = g_scan[i] - cnt + (b ? g_partS[b - 1] : 0);
    float d = (float)cnt + 1.0f;
    g_dinv[i]  = 1.0f / d;
    g_dinvs[i] = rsqrtf(d);
}

__global__ void k_fill(const int* __restrict__ src, const int* __restrict__ dst) {
    int e = blockIdx.x * blockDim.x + threadIdx.x;
    if (e >= EE) return;
    int s = src[e], d = dst[e];
    int slot = g_rows[d] + atomicAdd(&g_cur[d], 1);
    g_csr_src[slot] = s;
    g_csr_w[slot]   = g_dinvs[s] * g_dinvs[d];
}

// ======== GEMM: [M,128] @ [128,128], 3-pass split-bf16 mma.sync =============
// A from fp32 (convert+split in kernel). W pre-split, loaded via cp.async.
// mode 0: g_x = X @ W + bias     mode 1: g_xw = g_x @ W
#define GSTRIDE 272
#define GTILE   (128 * GSTRIDE)
#define OFF_AHI 0
#define OFF_ALO (GTILE)
#define OFF_WHI (2 * GTILE)
#define OFF_WLO (3 * GTILE)
#define GSMEM   (4 * GTILE)              // 139264 B

__global__ void __launch_bounds__(256, 1)
k_gemm_mma(const float* __restrict__ Xext,
           const float* __restrict__ bias,
           int M, int mode, int wslot)
{
    extern __shared__ char smem[];
    const uint32_t smb = smem_u32(smem);
    const int tid  = threadIdx.x;
    const int row0 = blockIdx.x * 128;

    const __nv_bfloat16* Wh = g_wh + wslot * HIDD * HIDD;
    const __nv_bfloat16* Wl = g_wl + wslot * HIDD * HIDD;

    // ---- W tiles via cp.async (bf16, pre-split) ----
    #pragma unroll
    for (int t = 0; t < 8; t++) {
        int idx = tid + 256 * t;          // 0..2047
        int row = idx >> 4;
        int c   = idx & 15;
        uint32_t so = row * GSTRIDE + c * 16;
        int ge = row * 128 + c * 8;
        cp16(smb + OFF_WHI + so, Wh + ge);
        cp16(smb + OFF_WLO + so, Wl + ge);
    }

    // ---- A tile: fp32 -> bf16 hi/lo, zero-pad OOB rows ----
    {
        const float* X = (mode == 0) ? Xext : g_x;
        const float2* X2 = reinterpret_cast<const float2*>(X);
        #pragma unroll
        for (int i = 0; i < 32; i++) {
            int idx = tid + 256 * i;
            int row = idx >> 6;
            int kp  = idx & 63;
            int gr  = row0 + row;
            float2 v = (gr < M) ? X2[gr * 64 + kp] : make_float2(0.f, 0.f);
            __nv_bfloat162 h2 = __float22bfloat162_rn(v);
            float2 hf = __bfloat1622float2(h2);
            __nv_bfloat162 l2 = __float22bfloat162_rn(
                                   make_float2(v.x - hf.x, v.y - hf.y));
            int off = row * GSTRIDE + kp * 4;
            *reinterpret_cast<uint32_t*>(smem + OFF_AHI + off) =
                *reinterpret_cast<uint32_t*>(&h2);
            *reinterpret_cast<uint32_t*>(smem + OFF_ALO + off) =
                *reinterpret_cast<uint32_t*>(&l2);
        }
    }
    cp_commit_wait();
    __syncthreads();

    const int wid  = tid >> 5;
    const int lane = tid & 31;
    const int mb   = (wid >> 1) * 32;
    const int nb   = (wid & 1) * 64;

    const int a_r  = lane & 15;
    const int a_kb = (lane >> 4) << 4;
    const int b_r  = lane & 7;
    const int b_kh = ((lane >> 3) & 1) << 3;
    const int b_nh = ((lane >> 4) & 1) << 3;

    float acc[2][8][4];
    #pragma unroll
    for (int mt = 0; mt < 2; mt++)
        #pragma unroll
        for (int nt = 0; nt < 8; nt++)
            #pragma unroll
            for (int q = 0; q < 4; q++) acc[mt][nt][q] = 0.f;

    const uint32_t passA[3] = {OFF_AHI, OFF_AHI, OFF_ALO};
    const uint32_t passB[3] = {OFF_WHI, OFF_WLO, OFF_WHI};

    #pragma unroll
    for (int p = 0; p < 3; p++) {
        uint32_t Ab = smb + passA[p];
        uint32_t Bb = smb + passB[p];
        #pragma unroll
        for (int ks = 0; ks < 8; ks++) {
            uint32_t a[2][4];
            ldm_x4(a[0], Ab + (mb + a_r) * GSTRIDE + ks * 32 + a_kb);
            ldm_x4(a[1], Ab + (mb + 16 + a_r) * GSTRIDE + ks * 32 + a_kb);
            #pragma unroll
            for (int np = 0; np < 4; np++) {
                uint32_t b[4];
                ldm_x4_t(b, Bb + (ks * 16 + b_kh + b_r) * GSTRIDE
                             + (nb + np * 16 + b_nh) * 2);
                mma_bf16(acc[0][np*2],   a[0], b[0], b[1]);
                mma_bf16(acc[0][np*2+1], a[0], b[2], b[3]);
                mma_bf16(acc[1][np*2],   a[1], b[0], b[1]);
                mma_bf16(acc[1][np*2+1], a[1], b[2], b[3]);
            }
        }
    }

    // ---- epilogue ----
    float* dst = (mode == 0) ? g_x : g_xw;
    const int tq = lane >> 2;
    const int tr = (lane & 3) * 2;
    #pragma unroll
    for (int mt = 0; mt < 2; mt++) {
        int rbase = row0 + mb + mt * 16 + tq;
        #pragma unroll
        for (int nt = 0; nt < 8; nt++) {
            int col = nb + nt * 8 + tr;
            float2 v0 = make_float2(acc[mt][nt][0], acc[mt][nt][1]);
            float2 v1 = make_float2(acc[mt][nt][2], acc[mt][nt][3]);
            if (mode == 0) {
                float2 bv = *reinterpret_cast<const float2*>(&bias[col]);
                v0.x += bv.x; v0.y += bv.y;
                v1.x += bv.x; v1.y += bv.y;
            }
            if (rbase < M)
                *reinterpret_cast<float2*>(&dst[rbase * 128 + col]) = v0;
            if (rbase + 8 < M)
                *reinterpret_cast<float2*>(&dst[(rbase + 8) * 128 + col]) = v1;
        }
    }
}

// ------- fused: CSR gather-aggregate + self-loop + bias + LN + ReLU + res ---
__global__ void k_aggln(const float* __restrict__ bias,
                        const float* __restrict__ gamma,
                        const float* __restrict__ beta,
                        float* __restrict__ dout,
                        int add_res, int write_out)
{
    int t = blockIdx.x * blockDim.x + threadIdx.x;
    int n    = t >> 5;
    int lane = t & 31;
    if (n >= NN) return;

    const float4* xw4 = reinterpret_cast<const float4*>(g_xw);

    float di  = g_dinv[n];
    float4 sv = xw4[n * 32 + lane];
    float4 acc = make_float4(sv.x * di, sv.y * di, sv.z * di, sv.w * di);

    int beg = g_rows[n];
    int end = beg + g_ecnt[n];
    int k = beg;
    for (; k + 4 <= end; k += 4) {
        int   s0 = g_csr_src[k],   s1 = g_csr_src[k+1];
        int   s2 = g_csr_src[k+2], s3 = g_csr_src[k+3];
        float w0 = g_csr_w[k],   w1 = g_csr_w[k+1];
        float w2 = g_csr_w[k+2], w3 = g_csr_w[k+3];
        float4 v0 = xw4[s0 * 32 + lane];
        float4 v1 = xw4[s1 * 32 + lane];
        float4 v2 = xw4[s2 * 32 + lane];
        float4 v3 = xw4[s3 * 32 + lane];
        acc.x = fmaf(v0.x, w0, fmaf(v1.x, w1, fmaf(v2.x, w2, fmaf(v3.x, w3, acc.x))));
        acc.y = fmaf(v0.y, w0, fmaf(v1.y, w1, fmaf(v2.y, w2, fmaf(v3.y, w3, acc.y))));
        acc.z = fmaf(v0.z, w0, fmaf(v1.z, w1, fmaf(v2.z, w2, fmaf(v3.z, w3, acc.z))));
        acc.w = fmaf(v0.w, w0, fmaf(v1.w, w1, fmaf(v2.w, w2, fmaf(v3.w, w3, acc.w))));
    }
    for (; k < end; k++) {
        int s = g_csr_src[k];
        float w = g_csr_w[k];
        float4 v = xw4[s * 32 + lane];
        acc.x = fmaf(v.x, w, acc.x);
        acc.y = fmaf(v.y, w, acc.y);
        acc.z = fmaf(v.z, w, acc.z);
        acc.w = fmaf(v.w, w, acc.w);
    }

    float4 bv = reinterpret_cast<const float4*>(bias)[lane];
    acc.x += bv.x; acc.y += bv.y; acc.z += bv.z; acc.w += bv.w;

    float s = acc.x + acc.y + acc.z + acc.w;
    float q = acc.x*acc.x + acc.y*acc.y + acc.z*acc.z + acc.w*acc.w;
    #pragma unroll
    for (int o = 16; o; o >>= 1) {
        s += __shfl_xor_sync(0xffffffffu, s, o);
        q += __shfl_xor_sync(0xffffffffu, q, o);
    }
    float mu  = s * (1.0f / 128.0f);
    float var = q * (1.0f / 128.0f) - mu * mu;
    float rs  = rsqrtf(var + EPSV);

    float4 gg = reinterpret_cast<const float4*>(gamma)[lane];
    float4 bt = reinterpret_cast<const float4*>(beta)[lane];
    float4 y;
    y.x = fmaxf(fmaf((acc.x - mu) * rs, gg.x, bt.x), 0.f);
    y.y = fmaxf(fmaf((acc.y - mu) * rs, gg.y, bt.y), 0.f);
    y.z = fmaxf(fmaf((acc.z - mu) * rs, gg.z, bt.z), 0.f);
    y.w = fmaxf(fmaf((acc.w - mu) * rs, gg.w, bt.w), 0.f);

    if (add_res) {
        float4 r = reinterpret_cast<const float4*>(g_x)[n * 32 + lane];
        y.x += r.x; y.y += r.y; y.z += r.z; y.w += r.w;
    }
    reinterpret_cast<float4*>(g_x)[n * 32 + lane] = y;
    if (write_out)
        reinterpret_cast<float4*>(dout)[n * 32 + lane] = y;
}

// ---------------- global mean pool ------------------------------------------
__global__ void k_pool(const int* __restrict__ batch_idx) {
    int t = blockIdx.x * blockDim.x + threadIdx.x;
    int n = t >> 5;
    int j = t & 31;
    if (n >= NN) return;
    int b = batch_idx[n];
    float4 v = reinterpret_cast<const float4*>(g_x)[n * 32 + j];
    red_add_v4(&g_pool[b * 128 + j * 4], v);
    if (j == 0) atomicAdd(&g_cnt[b], 1.0f);
}

__global__ void k_poolfin(float* __restrict__ dout) {
    int i = blockIdx.x * blockDim.x + threadIdx.x;
    if (i >= BB * HIDD) return;
    int b = i >> 7;
    dout[NN * HIDD + i] = g_pool[i] / fmaxf(g_cnt[b], 1.0f);
}

// ---------------- launch ------------------------------------------------------
extern "C" void kernel_launch(void* const* d_in, const int* in_sizes, int n_in,
                              void* d_out, int out_size)
{
    const float* nodes     = (const float*)d_in[0];
    const int*   edges     = (const int*)  d_in[1];
    const int*   batch_idx = (const int*)  d_in[3];
    const float* w_in      = (const float*)d_in[4];
    const float* b_in      = (const float*)d_in[5];
    const float* gcn_w     = (const float*)d_in[6];
    const float* gcn_b     = (const float*)d_in[7];
    const float* ln_g      = (const float*)d_in[8];
    const float* ln_b      = (const float*)d_in[9];
    float*       out       = (float*)d_out;

    const int* src = edges;
    const int* dst = edges + EE;

    static cudaStream_t s2 = nullptr;
    static cudaEvent_t ev_fork = nullptr, ev_join = nullptr;
    static bool attr_set = false;
    if (!attr_set) {
        cudaFuncSetAttribute(k_gemm_mma,
                             cudaFuncAttributeMaxDynamicSharedMemorySize, GSMEM);
        cudaStreamCreateWithFlags(&s2, cudaStreamNonBlocking);
        cudaEventCreateWithFlags(&ev_fork, cudaEventDisableTiming);
        cudaEventCreateWithFlags(&ev_join, cudaEventDisableTiming);
        attr_set = true;
    }

    const int T = 256;
    const int INIT_N = (NN > BB * HIDD) ? NN : (BB * HIDD);
    const int GEMM_GRID = (NN + 127) / 128;

    // fork: side stream does wconv + input-projection GEMM
    cudaEventRecord(ev_fork, 0);
    cudaStreamWaitEvent(s2, ev_fork, 0);
    k_wconv<<<(4 * HIDD * HIDD + T - 1) / T, T, 0, s2>>>(w_in, gcn_w);
    k_gemm_mma<<<GEMM_GRID, T, GSMEM, s2>>>(nodes, b_in, NN, 0, 0);
    cudaEventRecord(ev_join, s2);

    // main stream: CSR prep chain
    k_init <<<(INIT_N + T - 1) / T, T>>>();
    k_deg  <<<(EE + T - 1) / T, T>>>(dst);
    k_scan_blk<<<NPART, 1024>>>();
    k_scan_top<<<1, 32>>>();
    k_scan_fin<<<(NN + T - 1) / T, T>>>();
    k_fill<<<(EE + T - 1) / T, T>>>(src, dst);

    // join before layer loop
    cudaStreamWaitEvent(0, ev_join, 0);

    for (int i = 0; i < LLAY; i++) {
        k_gemm_mma<<<GEMM_GRID, T, GSMEM>>>(nullptr, nullptr, NN, 1, i + 1);
        k_aggln<<<(NN * 32 + T - 1) / T, T>>>(gcn_b + i * HIDD,
                                              ln_g + i * HIDD, ln_b + i * HIDD,
                                              out, (i > 0) ? 1 : 0,
                                              (i == LLAY - 1) ? 1 : 0);
    }

    k_pool   <<<(NN * 32 + T - 1) / T, T>>>(batch_idx);
    k_poolfin<<<(BB * HIDD + T - 1) / T, T>>>(out);
}

// round 9
// speedup vs baseline: 1.0847x; 1.0468x over previous
#include <cuda_runtime.h>
#include <cuda_bf16.h>
#include <math.h>
#include <stdint.h>

#define NN    100000
#define EE    1600000
#define HIDD  128
#define BB    512
#define LLAY  3
#define EPSV  1e-5f
#define NPART ((NN + 1023) / 1024)

// ---------------- scratch (device globals; allocation-free) ----------------
__device__ __align__(16) float g_x  [NN * HIDD];
__device__ __align__(16) float g_xw [NN * HIDD];
__device__ __align__(16) __nv_bfloat16 g_wh[4 * HIDD * HIDD];
__device__ __align__(16) __nv_bfloat16 g_wl[4 * HIDD * HIDD];
__device__ __align__(16) float g_dinv [NN];
__device__ __align__(16) float g_dinvs[NN];
__device__ __align__(16) float g_pool[BB * HIDD];
__device__ __align__(16) float g_cnt [BB];
// CSR
__device__ int   g_ecnt[NN];
__device__ int   g_cur [NN];
__device__ int   g_scan[NN];
__device__ int   g_rows[NN];
__device__ int   g_part [NPART];
__device__ int   g_partS[NPART];
__device__ int   g_csr_src[EE];
__device__ float g_csr_w  [EE];

// ---------------- helpers ----------------
__device__ __forceinline__ void red_add_v4(float* p, float4 v) {
    asm volatile("red.global.add.v4.f32 [%0], {%1, %2, %3, %4};"
                 :: "l"(p), "f"(v.x), "f"(v.y), "f"(v.z), "f"(v.w)
                 : "memory");
}
__device__ __forceinline__ uint32_t smem_u32(const void* p) {
    uint32_t a;
    asm("{ .reg .u64 t; cvta.to.shared.u64 t, %1; cvt.u32.u64 %0, t; }"
        : "=r"(a) : "l"(p));
    return a;
}
__device__ __forceinline__ void cp16(uint32_t smaddr, const void* g) {
    asm volatile("cp.async.cg.shared.global [%0], [%1], 16;"
                 :: "r"(smaddr), "l"(g) : "memory");
}
__device__ __forceinline__ void cp_commit_wait() {
    asm volatile("cp.async.commit_group;" ::: "memory");
    asm volatile("cp.async.wait_group 0;" ::: "memory");
}
__device__ __forceinline__ void ldm_x4(uint32_t* r, uint32_t addr) {
    asm volatile("ldmatrix.sync.aligned.m8n8.x4.shared.b16 {%0,%1,%2,%3}, [%4];"
                 : "=r"(r[0]), "=r"(r[1]), "=r"(r[2]), "=r"(r[3]) : "r"(addr));
}
__device__ __forceinline__ void ldm_x4_t(uint32_t* r, uint32_t addr) {
    asm volatile("ldmatrix.sync.aligned.m8n8.x4.trans.shared.b16 {%0,%1,%2,%3}, [%4];"
                 : "=r"(r[0]), "=r"(r[1]), "=r"(r[2]), "=r"(r[3]) : "r"(addr));
}
__device__ __forceinline__ void mma_bf16(float* c, const uint32_t* a,
                                         uint32_t b0, uint32_t b1) {
    asm volatile(
        "mma.sync.aligned.m16n8k16.row.col.f32.bf16.bf16.f32 "
        "{%0,%1,%2,%3}, {%4,%5,%6,%7}, {%8,%9}, {%0,%1,%2,%3};"
        : "+f"(c[0]), "+f"(c[1]), "+f"(c[2]), "+f"(c[3])
        : "r"(a[0]), "r"(a[1]), "r"(a[2]), "r"(a[3]), "r"(b0), "r"(b1));
}

// ---------------- init (covers all of NN — graph-replay determinism) --------
__global__ void k_init() {
    int i = blockIdx.x * blockDim.x + threadIdx.x;
    if (i < NN)        { g_ecnt[i] = 0; g_cur[i] = 0; }
    if (i < BB * HIDD) g_pool[i] = 0.0f;
    if (i < BB)        g_cnt[i]  = 0.0f;
}

// ---------------- pre-split all weight matrices to bf16 hi/lo ---------------
__global__ void k_wconv(const float* __restrict__ w_in,
                        const float* __restrict__ gcn_w) {
    int i = blockIdx.x * blockDim.x + threadIdx.x;
    if (i >= 4 * HIDD * HIDD) return;
    float v = (i < HIDD * HIDD) ? w_in[i] : gcn_w[i - HIDD * HIDD];
    __nv_bfloat16 h = __float2bfloat16(v);
    g_wh[i] = h;
    g_wl[i] = __float2bfloat16(v - __bfloat162float(h));
}

// 4-way ILP degree count
__global__ void k_deg(const int* __restrict__ dst) {
    int base = blockIdx.x * blockDim.x * 4 + threadIdx.x;
    int stride = blockDim.x;
    int d0 = -1, d1 = -1, d2 = -1, d3 = -1;
    if (base               < EE) d0 = dst[base];
    if (base +     stride  < EE) d1 = dst[base + stride];
    if (base + 2 * stride  < EE) d2 = dst[base + 2 * stride];
    if (base + 3 * stride  < EE) d3 = dst[base + 3 * stride];
    if (d0 >= 0) atomicAdd(&g_ecnt[d0], 1);
    if (d1 >= 0) atomicAdd(&g_ecnt[d1], 1);
    if (d2 >= 0) atomicAdd(&g_ecnt[d2], 1);
    if (d3 >= 0) atomicAdd(&g_ecnt[d3], 1);
}

// ---------------- scan / CSR build ----------------
__global__ void k_scan_blk() {
    __shared__ int sm[1024];
    int i = blockIdx.x * 1024 + threadIdx.x;
    int v = (i < NN) ? g_ecnt[i] : 0;
    sm[threadIdx.x] = v;
    __syncthreads();
    #pragma unroll
    for (int off = 1; off < 1024; off <<= 1) {
        int t = (threadIdx.x >= off) ? sm[threadIdx.x - off] : 0;
        __syncthreads();
        sm[threadIdx.x] += t;
        __syncthreads();
    }
    if (i < NN) g_scan[i] = sm[threadIdx.x];
    if (threadIdx.x == 1023) g_part[blockIdx.x] = sm[1023];
}

__global__ void k_scan_top() {
    if (threadIdx.x == 0) {
        int s = 0;
        for (int b = 0; b < NPART; b++) { s += g_part[b]; g_partS[b] = s; }
    }
}

// fused: row offsets + degree norms
__global__ void k_scan_fin() {
    int i = blockIdx.x * blockDim.x + threadIdx.x;
    if (i >= NN) return;
    int b = i >> 10;
    int cnt = g_ecnt[i];
    g_rows[i] = g_scan[i] - cnt + (b ? g_partS[b - 1] : 0);
    float d = (float)cnt + 1.0f;
    g_dinv[i]  = 1.0f / d;
    g_dinvs[i] = rsqrtf(d);
}

__global__ void k_fill(const int* __restrict__ src, const int* __restrict__ dst) {
    int e = blockIdx.x * blockDim.x + threadIdx.x;
    if (e >= EE) return;
    int s = src[e], d = dst[e];
    int slot = g_rows[d] + atomicAdd(&g_cur[d], 1);
    g_csr_src[slot] = s;
    g_csr_w[slot]   = g_dinvs[s] * g_dinvs[d];
}

// ======== GEMM: [M,128] @ [128,128], 3-pass split-bf16 mma.sync =============
// 64-row block tiles, 102 KB smem -> 2 CTAs/SM for latency overlap.
// mode 0: g_x = X @ W + bias     mode 1: g_xw = g_x @ W
#define GSTRIDE 272
#define ATILE   (64 * GSTRIDE)           // 17408
#define WTILE   (128 * GSTRIDE)          // 34816
#define OFF_AHI 0
#define OFF_ALO (ATILE)
#define OFF_WHI (2 * ATILE)
#define OFF_WLO (2 * ATILE + WTILE)
#define GSMEM   (2 * ATILE + 2 * WTILE)  // 104448 B

__global__ void __launch_bounds__(256, 2)
k_gemm_mma(const float* __restrict__ Xext,
           const float* __restrict__ bias,
           int M, int mode, int wslot)
{
    extern __shared__ char smem[];
    const uint32_t smb = smem_u32(smem);
    const int tid  = threadIdx.x;
    const int row0 = blockIdx.x * 64;

    const __nv_bfloat16* Wh = g_wh + wslot * HIDD * HIDD;
    const __nv_bfloat16* Wl = g_wl + wslot * HIDD * HIDD;

    // ---- W tiles via cp.async (bf16, pre-split) ----
    #pragma unroll
    for (int t = 0; t < 8; t++) {
        int idx = tid + 256 * t;          // 0..2047
        int row = idx >> 4;
        int c   = idx & 15;
        uint32_t so = row * GSTRIDE + c * 16;
        int ge = row * 128 + c * 8;
        cp16(smb + OFF_WHI + so, Wh + ge);
        cp16(smb + OFF_WLO + so, Wl + ge);
    }

    // ---- A tile (64 rows): fp32 -> bf16 hi/lo, zero-pad OOB rows ----
    {
        const float* X = (mode == 0) ? Xext : g_x;
        const float2* X2 = reinterpret_cast<const float2*>(X);
        #pragma unroll
        for (int i = 0; i < 16; i++) {
            int idx = tid + 256 * i;      // 0..4095
            int row = idx >> 6;
            int kp  = idx & 63;
            int gr  = row0 + row;
            float2 v = (gr < M) ? X2[gr * 64 + kp] : make_float2(0.f, 0.f);
            __nv_bfloat162 h2 = __float22bfloat162_rn(v);
            float2 hf = __bfloat1622float2(h2);
            __nv_bfloat162 l2 = __float22bfloat162_rn(
                                   make_float2(v.x - hf.x, v.y - hf.y));
            int off = row * GSTRIDE + kp * 4;
            *reinterpret_cast<uint32_t*>(smem + OFF_AHI + off) =
                *reinterpret_cast<uint32_t*>(&h2);
            *reinterpret_cast<uint32_t*>(smem + OFF_ALO + off) =
                *reinterpret_cast<uint32_t*>(&l2);
        }
    }
    cp_commit_wait();
    __syncthreads();

    const int wid  = tid >> 5;
    const int lane = tid & 31;
    const int mb   = (wid >> 1) * 16;     // 4 x 16-row strips
    const int nb   = (wid & 1) * 64;      // 2 x 64-col strips

    const int a_r  = lane & 15;
    const int a_kb = (lane >> 4) << 4;
    const int b_r  = lane & 7;
    const int b_kh = ((lane >> 3) & 1) << 3;
    const int b_nh = ((lane >> 4) & 1) << 3;

    float acc[8][4];
    #pragma unroll
    for (int nt = 0; nt < 8; nt++)
        #pragma unroll
        for (int q = 0; q < 4; q++) acc[nt][q] = 0.f;

    const uint32_t passA[3] = {OFF_AHI, OFF_AHI, OFF_ALO};
    const uint32_t passB[3] = {OFF_WHI, OFF_WLO, OFF_WHI};

    #pragma unroll
    for (int p = 0; p < 3; p++) {
        uint32_t Ab = smb + passA[p];
        uint32_t Bb = smb + passB[p];
        #pragma unroll
        for (int ks = 0; ks < 8; ks++) {
            uint32_t a[4];
            ldm_x4(a, Ab + (mb + a_r) * GSTRIDE + ks * 32 + a_kb);
            #pragma unroll
            for (int np = 0; np < 4; np++) {
                uint32_t b[4];
                ldm_x4_t(b, Bb + (ks * 16 + b_kh + b_r) * GSTRIDE
                             + (nb + np * 16 + b_nh) * 2);
                mma_bf16(acc[np*2],   a, b[0], b[1]);
                mma_bf16(acc[np*2+1], a, b[2], b[3]);
            }
        }
    }

    // ---- epilogue ----
    float* dst = (mode == 0) ? g_x : g_xw;
    const int tq = lane >> 2;
    const int tr = (lane & 3) * 2;
    int rbase = row0 + mb + tq;
    #pragma unroll
    for (int nt = 0; nt < 8; nt++) {
        int col = nb + nt * 8 + tr;
        float2 v0 = make_float2(acc[nt][0], acc[nt][1]);
        float2 v1 = make_float2(acc[nt][2], acc[nt][3]);
        if (mode == 0) {
            float2 bv = *reinterpret_cast<const float2*>(&bias[col]);
            v0.x += bv.x; v0.y += bv.y;
            v1.x += bv.x; v1.y += bv.y;
        }
        if (rbase < M)
            *reinterpret_cast<float2*>(&dst[rbase * 128 + col]) = v0;
        if (rbase + 8 < M)
            *reinterpret_cast<float2*>(&dst[(rbase + 8) * 128 + col]) = v1;
    }
}

// ------- fused: CSR gather-aggregate + self-loop + bias + LN + ReLU + res ---
// final layer (write_out): also writes dout and does mean-pool accumulation;
// skips the g_x write (dead after pool fusion).
__global__ void k_aggln(const float* __restrict__ bias,
                        const float* __restrict__ gamma,
                        const float* __restrict__ beta,
                        float* __restrict__ dout,
                        const int* __restrict__ batch_idx,
                        int add_res, int write_out)
{
    int t = blockIdx.x * blockDim.x + threadIdx.x;
    int n    = t >> 5;
    int lane = t & 31;
    if (n >= NN) return;

    const float4* xw4 = reinterpret_cast<const float4*>(g_xw);

    float di  = g_dinv[n];
    float4 sv = xw4[n * 32 + lane];
    float4 acc = make_float4(sv.x * di, sv.y * di, sv.z * di, sv.w * di);

    int beg = g_rows[n];
    int end = beg + g_ecnt[n];
    int k = beg;
    for (; k + 4 <= end; k += 4) {
        int   s0 = g_csr_src[k],   s1 = g_csr_src[k+1];
        int   s2 = g_csr_src[k+2], s3 = g_csr_src[k+3];
        float w0 = g_csr_w[k],   w1 = g_csr_w[k+1];
        float w2 = g_csr_w[k+2], w3 = g_csr_w[k+3];
        float4 v0 = xw4[s0 * 32 + lane];
        float4 v1 = xw4[s1 * 32 + lane];
        float4 v2 = xw4[s2 * 32 + lane];
        float4 v3 = xw4[s3 * 32 + lane];
        acc.x = fmaf(v0.x, w0, fmaf(v1.x, w1, fmaf(v2.x, w2, fmaf(v3.x, w3, acc.x))));
        acc.y = fmaf(v0.y, w0, fmaf(v1.y, w1, fmaf(v2.y, w2, fmaf(v3.y, w3, acc.y))));
        acc.z = fmaf(v0.z, w0, fmaf(v1.z, w1, fmaf(v2.z, w2, fmaf(v3.z, w3, acc.z))));
        acc.w = fmaf(v0.w, w0, fmaf(v1.w, w1, fmaf(v2.w, w2, fmaf(v3.w, w3, acc.w))));
    }
    for (; k < end; k++) {
        int s = g_csr_src[k];
        float w = g_csr_w[k];
        float4 v = xw4[s * 32 + lane];
        acc.x = fmaf(v.x, w, acc.x);
        acc.y = fmaf(v.y, w, acc.y);
        acc.z = fmaf(v.z, w, acc.z);
        acc.w = fmaf(v.w, w, acc.w);
    }

    float4 bv = reinterpret_cast<const float4*>(bias)[lane];
    acc.x += bv.x; acc.y += bv.y; acc.z += bv.z; acc.w += bv.w;

    float s = acc.x + acc.y + acc.z + acc.w;
    float q = acc.x*acc.x + acc.y*acc.y + acc.z*acc.z + acc.w*acc.w;
    #pragma unroll
    for (int o = 16; o; o >>= 1) {
        s += __shfl_xor_sync(0xffffffffu, s, o);
        q += __shfl_xor_sync(0xffffffffu, q, o);
    }
    float mu  = s * (1.0f / 128.0f);
    float var = q * (1.0f / 128.0f) - mu * mu;
    float rs  = rsqrtf(var + EPSV);

    float4 gg = reinterpret_cast<const float4*>(gamma)[lane];
    float4 bt = reinterpret_cast<const float4*>(beta)[lane];
    float4 y;
    y.x = fmaxf(fmaf((acc.x - mu) * rs, gg.x, bt.x), 0.f);
    y.y = fmaxf(fmaf((acc.y - mu) * rs, gg.y, bt.y), 0.f);
    y.z = fmaxf(fmaf((acc.z - mu) * rs, gg.z, bt.z), 0.f);
    y.w = fmaxf(fmaf((acc.w - mu) * rs, gg.w, bt.w), 0.f);

    if (add_res) {
        float4 r = reinterpret_cast<const float4*>(g_x)[n * 32 + lane];
        y.x += r.x; y.y += r.y; y.z += r.z; y.w += r.w;
    }

    if (write_out) {
        reinterpret_cast<float4*>(dout)[n * 32 + lane] = y;
        int b = batch_idx[n];
        red_add_v4(&g_pool[b * 128 + lane * 4], y);
        if (lane == 0) atomicAdd(&g_cnt[b], 1.0f);
    } else {
        reinterpret_cast<float4*>(g_x)[n * 32 + lane] = y;
    }
}

__global__ void k_poolfin(float* __restrict__ dout) {
    int i = blockIdx.x * blockDim.x + threadIdx.x;
    if (i >= BB * HIDD) return;
    int b = i >> 7;
    dout[NN * HIDD + i] = g_pool[i] / fmaxf(g_cnt[b], 1.0f);
}

// ---------------- launch ------------------------------------------------------
extern "C" void kernel_launch(void* const* d_in, const int* in_sizes, int n_in,
                              void* d_out, int out_size)
{
    const float* nodes     = (const float*)d_in[0];
    const int*   edges     = (const int*)  d_in[1];
    const int*   batch_idx = (const int*)  d_in[3];
    const float* w_in      = (const float*)d_in[4];
    const float* b_in      = (const float*)d_in[5];
    const float* gcn_w     = (const float*)d_in[6];
    const float* gcn_b     = (const float*)d_in[7];
    const float* ln_g      = (const float*)d_in[8];
    const float* ln_b      = (const float*)d_in[9];
    float*       out       = (float*)d_out;

    const int* src = edges;
    const int* dst = edges + EE;

    static cudaStream_t s2 = nullptr;
    static cudaEvent_t ev_fork = nullptr, ev_join = nullptr;
    static bool attr_set = false;
    if (!attr_set) {
        cudaFuncSetAttribute(k_gemm_mma,
                             cudaFuncAttributeMaxDynamicSharedMemorySize, GSMEM);
        cudaStreamCreateWithFlags(&s2, cudaStreamNonBlocking);
        cudaEventCreateWithFlags(&ev_fork, cudaEventDisableTiming);
        cudaEventCreateWithFlags(&ev_join, cudaEventDisableTiming);
        attr_set = true;
    }

    const int T = 256;
    const int INIT_N = (NN > BB * HIDD) ? NN : (BB * HIDD);
    const int GEMM_GRID = (NN + 63) / 64;

    // fork: side stream does wconv + input-projection GEMM
    cudaEventRecord(ev_fork, 0);
    cudaStreamWaitEvent(s2, ev_fork, 0);
    k_wconv<<<(4 * HIDD * HIDD + T - 1) / T, T, 0, s2>>>(w_in, gcn_w);
    k_gemm_mma<<<GEMM_GRID, T, GSMEM, s2>>>(nodes, b_in, NN, 0, 0);
    cudaEventRecord(ev_join, s2);

    // main stream: CSR prep chain
    k_init <<<(INIT_N + T - 1) / T, T>>>();
    k_deg  <<<(EE + T * 4 - 1) / (T * 4), T>>>(dst);
    k_scan_blk<<<NPART, 1024>>>();
    k_scan_top<<<1, 32>>>();
    k_scan_fin<<<(NN + T - 1) / T, T>>>();
    k_fill<<<(EE + T - 1) / T, T>>>(src, dst);

    // join before layer loop
    cudaStreamWaitEvent(0, ev_join, 0);

    for (int i = 0; i < LLAY; i++) {
        k_gemm_mma<<<GEMM_GRID, T, GSMEM>>>(nullptr, nullptr, NN, 1, i + 1);
        k_aggln<<<(NN * 32 + T - 1) / T, T>>>(gcn_b + i * HIDD,
                                              ln_g + i * HIDD, ln_b + i * HIDD,
                                              out, batch_idx,
                                              (i > 0) ? 1 : 0,
                                              (i == LLAY - 1) ? 1 : 0);
    }

    k_poolfin<<<(BB * HIDD + T - 1) / T, T>>>(out);
}

// round 10
// speedup vs baseline: 1.1545x; 1.0643x over previous
#include <cuda_runtime.h>
#include <cuda_bf16.h>
#include <math.h>
#include <stdint.h>

#define NN    100000
#define EE    1600000
#define HIDD  128
#define BB    512
#define LLAY  3
#define EPSV  1e-5f
#define NPART ((NN + 1023) / 1024)

// ---------------- scratch (device globals; allocation-free) ----------------
__device__ __align__(16) float g_x  [NN * HIDD];
__device__ __align__(16) float g_xw [NN * HIDD];   // xw PRE-SCALED by dinvs[row]
__device__ __align__(16) __nv_bfloat16 g_wh[4 * HIDD * HIDD];
__device__ __align__(16) __nv_bfloat16 g_wl[4 * HIDD * HIDD];
__device__ __align__(16) float g_dinvs[NN];
__device__ __align__(16) float g_pool[BB * HIDD];
__device__ __align__(16) float g_cnt [BB];
// CSR
__device__ int   g_ecnt[NN];
__device__ int   g_cur [NN];
__device__ int   g_scan[NN];
__device__ int   g_rows[NN];
__device__ int   g_part [NPART];
__device__ int   g_partS[NPART];
__device__ int   g_csr_src[EE];

// ---------------- helpers ----------------
__device__ __forceinline__ void red_add_v4(float* p, float4 v) {
    asm volatile("red.global.add.v4.f32 [%0], {%1, %2, %3, %4};"
                 :: "l"(p), "f"(v.x), "f"(v.y), "f"(v.z), "f"(v.w)
                 : "memory");
}
__device__ __forceinline__ uint32_t smem_u32(const void* p) {
    uint32_t a;
    asm("{ .reg .u64 t; cvta.to.shared.u64 t, %1; cvt.u32.u64 %0, t; }"
        : "=r"(a) : "l"(p));
    return a;
}
__device__ __forceinline__ void cp16(uint32_t smaddr, const void* g) {
    asm volatile("cp.async.cg.shared.global [%0], [%1], 16;"
                 :: "r"(smaddr), "l"(g) : "memory");
}
__device__ __forceinline__ void cp_commit_wait() {
    asm volatile("cp.async.commit_group;" ::: "memory");
    asm volatile("cp.async.wait_group 0;" ::: "memory");
}
__device__ __forceinline__ void ldm_x4(uint32_t* r, uint32_t addr) {
    asm volatile("ldmatrix.sync.aligned.m8n8.x4.shared.b16 {%0,%1,%2,%3}, [%4];"
                 : "=r"(r[0]), "=r"(r[1]), "=r"(r[2]), "=r"(r[3]) : "r"(addr));
}
__device__ __forceinline__ void ldm_x4_t(uint32_t* r, uint32_t addr) {
    asm volatile("ldmatrix.sync.aligned.m8n8.x4.trans.shared.b16 {%0,%1,%2,%3}, [%4];"
                 : "=r"(r[0]), "=r"(r[1]), "=r"(r[2]), "=r"(r[3]) : "r"(addr));
}
__device__ __forceinline__ void mma_bf16(float* c, const uint32_t* a,
                                         uint32_t b0, uint32_t b1) {
    asm volatile(
        "mma.sync.aligned.m16n8k16.row.col.f32.bf16.bf16.f32 "
        "{%0,%1,%2,%3}, {%4,%5,%6,%7}, {%8,%9}, {%0,%1,%2,%3};"
        : "+f"(c[0]), "+f"(c[1]), "+f"(c[2]), "+f"(c[3])
        : "r"(a[0]), "r"(a[1]), "r"(a[2]), "r"(a[3]), "r"(b0), "r"(b1));
}

// ---------------- init (covers all of NN — graph-replay determinism) --------
__global__ void k_init() {
    int i = blockIdx.x * blockDim.x + threadIdx.x;
    if (i < NN)        { g_ecnt[i] = 0; g_cur[i] = 0; }
    if (i < BB * HIDD) g_pool[i] = 0.0f;
    if (i < BB)        g_cnt[i]  = 0.0f;
}

// ---------------- pre-split all weight matrices to bf16 hi/lo ---------------
__global__ void k_wconv(const float* __restrict__ w_in,
                        const float* __restrict__ gcn_w) {
    int i = blockIdx.x * blockDim.x + threadIdx.x;
    if (i >= 4 * HIDD * HIDD) return;
    float v = (i < HIDD * HIDD) ? w_in[i] : gcn_w[i - HIDD * HIDD];
    __nv_bfloat16 h = __float2bfloat16(v);
    g_wh[i] = h;
    g_wl[i] = __float2bfloat16(v - __bfloat162float(h));
}

// 4-way ILP degree count
__global__ void k_deg(const int* __restrict__ dst) {
    int base = blockIdx.x * blockDim.x * 4 + threadIdx.x;
    int stride = blockDim.x;
    int d0 = -1, d1 = -1, d2 = -1, d3 = -1;
    if (base               < EE) d0 = dst[base];
    if (base +     stride  < EE) d1 = dst[base + stride];
    if (base + 2 * stride  < EE) d2 = dst[base + 2 * stride];
    if (base + 3 * stride  < EE) d3 = dst[base + 3 * stride];
    if (d0 >= 0) atomicAdd(&g_ecnt[d0], 1);
    if (d1 >= 0) atomicAdd(&g_ecnt[d1], 1);
    if (d2 >= 0) atomicAdd(&g_ecnt[d2], 1);
    if (d3 >= 0) atomicAdd(&g_ecnt[d3], 1);
}

// ---------------- scan / CSR build ----------------
__global__ void k_scan_blk() {
    __shared__ int sm[1024];
    int i = blockIdx.x * 1024 + threadIdx.x;
    int v = (i < NN) ? g_ecnt[i] : 0;
    sm[threadIdx.x] = v;
    __syncthreads();
    #pragma unroll
    for (int off = 1; off < 1024; off <<= 1) {
        int t = (threadIdx.x >= off) ? sm[threadIdx.x - off] : 0;
        __syncthreads();
        sm[threadIdx.x] += t;
        __syncthreads();
    }
    if (i < NN) g_scan[i] = sm[threadIdx.x];
    if (threadIdx.x == 1023) g_part[blockIdx.x] = sm[1023];
}

__global__ void k_scan_top() {
    if (threadIdx.x == 0) {
        int s = 0;
        for (int b = 0; b < NPART; b++) { s += g_part[b]; g_partS[b] = s; }
    }
}

// fused: row offsets + degree norm
__global__ void k_scan_fin() {
    int i = blockIdx.x * blockDim.x + threadIdx.x;
    if (i >= NN) return;
    int b = i >> 10;
    int cnt = g_ecnt[i];
    g_rows[i] = g_scan[i] - cnt + (b ? g_partS[b - 1] : 0);
    g_dinvs[i] = rsqrtf((float)cnt + 1.0f);
}

__global__ void k_fill(const int* __restrict__ src, const int* __restrict__ dst) {
    int e = blockIdx.x * blockDim.x + threadIdx.x;
    if (e >= EE) return;
    int d = dst[e];
    int slot = g_rows[d] + atomicAdd(&g_cur[d], 1);
    g_csr_src[slot] = src[e];
}

// ======== GEMM: [M,128] @ [128,128], 3-pass split-bf16 mma.sync =============
// 64-row block tiles, 102 KB smem -> 2 CTAs/SM.
// mode 0: g_x  = X @ W + bias
// mode 1: g_xw = (g_x @ W) * dinvs[row]   (pre-scaled for the aggregation)
#define GSTRIDE 272
#define ATILE   (64 * GSTRIDE)
#define WTILE   (128 * GSTRIDE)
#define OFF_AHI 0
#define OFF_ALO (ATILE)
#define OFF_WHI (2 * ATILE)
#define OFF_WLO (2 * ATILE + WTILE)
#define GSMEM   (2 * ATILE + 2 * WTILE)  // 104448 B

__global__ void __launch_bounds__(256, 2)
k_gemm_mma(const float* __restrict__ Xext,
           const float* __restrict__ bias,
           int M, int mode, int wslot)
{
    extern __shared__ char smem[];
    const uint32_t smb = smem_u32(smem);
    const int tid  = threadIdx.x;
    const int row0 = blockIdx.x * 64;

    const __nv_bfloat16* Wh = g_wh + wslot * HIDD * HIDD;
    const __nv_bfloat16* Wl = g_wl + wslot * HIDD * HIDD;

    #pragma unroll
    for (int t = 0; t < 8; t++) {
        int idx = tid + 256 * t;
        int row = idx >> 4;
        int c   = idx & 15;
        uint32_t so = row * GSTRIDE + c * 16;
        int ge = row * 128 + c * 8;
        cp16(smb + OFF_WHI + so, Wh + ge);
        cp16(smb + OFF_WLO + so, Wl + ge);
    }

    {
        const float* X = (mode == 0) ? Xext : g_x;
        const float2* X2 = reinterpret_cast<const float2*>(X);
        #pragma unroll
        for (int i = 0; i < 16; i++) {
            int idx = tid + 256 * i;
            int row = idx >> 6;
            int kp  = idx & 63;
            int gr  = row0 + row;
            float2 v = (gr < M) ? X2[gr * 64 + kp] : make_float2(0.f, 0.f);
            __nv_bfloat162 h2 = __float22bfloat162_rn(v);
            float2 hf = __bfloat1622float2(h2);
            __nv_bfloat162 l2 = __float22bfloat162_rn(
                                   make_float2(v.x - hf.x, v.y - hf.y));
            int off = row * GSTRIDE + kp * 4;
            *reinterpret_cast<uint32_t*>(smem + OFF_AHI + off) =
                *reinterpret_cast<uint32_t*>(&h2);
            *reinterpret_cast<uint32_t*>(smem + OFF_ALO + off) =
                *reinterpret_cast<uint32_t*>(&l2);
        }
    }
    cp_commit_wait();
    __syncthreads();

    const int wid  = tid >> 5;
    const int lane = tid & 31;
    const int mb   = (wid >> 1) * 16;
    const int nb   = (wid & 1) * 64;

    const int a_r  = lane & 15;
    const int a_kb = (lane >> 4) << 4;
    const int b_r  = lane & 7;
    const int b_kh = ((lane >> 3) & 1) << 3;
    const int b_nh = ((lane >> 4) & 1) << 3;

    float acc[8][4];
    #pragma unroll
    for (int nt = 0; nt < 8; nt++)
        #pragma unroll
        for (int q = 0; q < 4; q++) acc[nt][q] = 0.f;

    const uint32_t passA[3] = {OFF_AHI, OFF_AHI, OFF_ALO};
    const uint32_t passB[3] = {OFF_WHI, OFF_WLO, OFF_WHI};

    #pragma unroll
    for (int p = 0; p < 3; p++) {
        uint32_t Ab = smb + passA[p];
        uint32_t Bb = smb + passB[p];
        #pragma unroll
        for (int ks = 0; ks < 8; ks++) {
            uint32_t a[4];
            ldm_x4(a, Ab + (mb + a_r) * GSTRIDE + ks * 32 + a_kb);
            #pragma unroll
            for (int np = 0; np < 4; np++) {
                uint32_t b[4];
                ldm_x4_t(b, Bb + (ks * 16 + b_kh + b_r) * GSTRIDE
                             + (nb + np * 16 + b_nh) * 2);
                mma_bf16(acc[np*2],   a, b[0], b[1]);
                mma_bf16(acc[np*2+1], a, b[2], b[3]);
            }
        }
    }

    // ---- epilogue ----
    float* dst = (mode == 0) ? g_x : g_xw;
    const int tq = lane >> 2;
    const int tr = (lane & 3) * 2;
    int rbase = row0 + mb + tq;
    float s0 = 1.f, s1 = 1.f;
    if (mode == 1) {
        if (rbase < M)     s0 = g_dinvs[rbase];
        if (rbase + 8 < M) s1 = g_dinvs[rbase + 8];
    }
    #pragma unroll
    for (int nt = 0; nt < 8; nt++) {
        int col = nb + nt * 8 + tr;
        float2 v0 = make_float2(acc[nt][0], acc[nt][1]);
        float2 v1 = make_float2(acc[nt][2], acc[nt][3]);
        if (mode == 0) {
            float2 bv = *reinterpret_cast<const float2*>(&bias[col]);
            v0.x += bv.x; v0.y += bv.y;
            v1.x += bv.x; v1.y += bv.y;
        } else {
            v0.x *= s0; v0.y *= s0;
            v1.x *= s1; v1.y *= s1;
        }
        if (rbase < M)
            *reinterpret_cast<float2*>(&dst[rbase * 128 + col]) = v0;
        if (rbase + 8 < M)
            *reinterpret_cast<float2*>(&dst[(rbase + 8) * 128 + col]) = v1;
    }
}

// ------- fused: gather-sum + dinvs scale + bias + LN + ReLU + res (+pool) ---
__global__ void k_aggln(const float* __restrict__ bias,
                        const float* __restrict__ gamma,
                        const float* __restrict__ beta,
                        float* __restrict__ dout,
                        const int* __restrict__ batch_idx,
                        int add_res, int write_out)
{
    int t = blockIdx.x * blockDim.x + threadIdx.x;
    int n    = t >> 5;
    int lane = t & 31;
    if (n >= NN) return;

    const float4* xw4 = reinterpret_cast<const float4*>(g_xw);

    // self-loop term (xw already scaled by dinvs[n])
    float4 acc = xw4[n * 32 + lane];

    int beg = g_rows[n];
    int end = beg + g_ecnt[n];
    int k = beg;
    for (; k + 4 <= end; k += 4) {
        int s0 = g_csr_src[k],   s1 = g_csr_src[k+1];
        int s2 = g_csr_src[k+2], s3 = g_csr_src[k+3];
        float4 v0 = xw4[s0 * 32 + lane];
        float4 v1 = xw4[s1 * 32 + lane];
        float4 v2 = xw4[s2 * 32 + lane];
        float4 v3 = xw4[s3 * 32 + lane];
        acc.x += (v0.x + v1.x) + (v2.x + v3.x);
        acc.y += (v0.y + v1.y) + (v2.y + v3.y);
        acc.z += (v0.z + v1.z) + (v2.z + v3.z);
        acc.w += (v0.w + v1.w) + (v2.w + v3.w);
    }
    for (; k < end; k++) {
        float4 v = xw4[g_csr_src[k] * 32 + lane];
        acc.x += v.x; acc.y += v.y; acc.z += v.z; acc.w += v.w;
    }

    float dn = g_dinvs[n];
    float4 bv = reinterpret_cast<const float4*>(bias)[lane];
    acc.x = fmaf(acc.x, dn, bv.x);
    acc.y = fmaf(acc.y, dn, bv.y);
    acc.z = fmaf(acc.z, dn, bv.z);
    acc.w = fmaf(acc.w, dn, bv.w);

    float s = acc.x + acc.y + acc.z + acc.w;
    float q = acc.x*acc.x + acc.y*acc.y + acc.z*acc.z + acc.w*acc.w;
    #pragma unroll
    for (int o = 16; o; o >>= 1) {
        s += __shfl_xor_sync(0xffffffffu, s, o);
        q += __shfl_xor_sync(0xffffffffu, q, o);
    }
    float mu  = s * (1.0f / 128.0f);
    float var = q * (1.0f / 128.0f) - mu * mu;
    float rs  = rsqrtf(var + EPSV);

    float4 gg = reinterpret_cast<const float4*>(gamma)[lane];
    float4 bt = reinterpret_cast<const float4*>(beta)[lane];
    float4 y;
    y.x = fmaxf(fmaf((acc.x - mu) * rs, gg.x, bt.x), 0.f);
    y.y = fmaxf(fmaf((acc.y - mu) * rs, gg.y, bt.y), 0.f);
    y.z = fmaxf(fmaf((acc.z - mu) * rs, gg.z, bt.z), 0.f);
    y.w = fmaxf(fmaf((acc.w - mu) * rs, gg.w, bt.w), 0.f);

    if (add_res) {
        float4 r = reinterpret_cast<const float4*>(g_x)[n * 32 + lane];
        y.x += r.x; y.y += r.y; y.z += r.z; y.w += r.w;
    }

    if (write_out) {
        reinterpret_cast<float4*>(dout)[n * 32 + lane] = y;
        int b = batch_idx[n];
        red_add_v4(&g_pool[b * 128 + lane * 4], y);
        if (lane == 0) atomicAdd(&g_cnt[b], 1.0f);
    } else {
        reinterpret_cast<float4*>(g_x)[n * 32 + lane] = y;
    }
}

__global__ void k_poolfin(float* __restrict__ dout) {
    int i = blockIdx.x * blockDim.x + threadIdx.x;
    if (i >= BB * HIDD) return;
    int b = i >> 7;
    dout[NN * HIDD + i] = g_pool[i] / fmaxf(g_cnt[b], 1.0f);
}

// ---------------- launch ------------------------------------------------------
extern "C" void kernel_launch(void* const* d_in, const int* in_sizes, int n_in,
                              void* d_out, int out_size)
{
    const float* nodes     = (const float*)d_in[0];
    const int*   edges     = (const int*)  d_in[1];
    const int*   batch_idx = (const int*)  d_in[3];
    const float* w_in      = (const float*)d_in[4];
    const float* b_in      = (const float*)d_in[5];
    const float* gcn_w     = (const float*)d_in[6];
    const float* gcn_b     = (const float*)d_in[7];
    const float* ln_g      = (const float*)d_in[8];
    const float* ln_b      = (const float*)d_in[9];
    float*       out       = (float*)d_out;

    const int* src = edges;
    const int* dst = edges + EE;

    static cudaStream_t s2 = nullptr;
    static cudaEvent_t ev_fork = nullptr, ev_mid = nullptr, ev_join = nullptr;
    static bool attr_set = false;
    if (!attr_set) {
        cudaFuncSetAttribute(k_gemm_mma,
                             cudaFuncAttributeMaxDynamicSharedMemorySize, GSMEM);
        cudaStreamCreateWithFlags(&s2, cudaStreamNonBlocking);
        cudaEventCreateWithFlags(&ev_fork, cudaEventDisableTiming);
        cudaEventCreateWithFlags(&ev_mid,  cudaEventDisableTiming);
        cudaEventCreateWithFlags(&ev_join, cudaEventDisableTiming);
        attr_set = true;
    }

    const int T = 256;
    const int INIT_N = (NN > BB * HIDD) ? NN : (BB * HIDD);
    const int GEMM_GRID = (NN + 63) / 64;

    // fork: side stream does wconv + input-projection GEMM
    cudaEventRecord(ev_fork, 0);
    cudaStreamWaitEvent(s2, ev_fork, 0);
    k_wconv<<<(4 * HIDD * HIDD + T - 1) / T, T, 0, s2>>>(w_in, gcn_w);
    k_gemm_mma<<<GEMM_GRID, T, GSMEM, s2>>>(nodes, b_in, NN, 0, 0);

    // main stream: CSR prep up through scan_fin (produces dinvs)
    k_init <<<(INIT_N + T - 1) / T, T>>>();
    k_deg  <<<(EE + T * 4 - 1) / (T * 4), T>>>(dst);
    k_scan_blk<<<NPART, 1024>>>();
    k_scan_top<<<1, 32>>>();
    k_scan_fin<<<(NN + T - 1) / T, T>>>();
    cudaEventRecord(ev_mid, 0);

    // side stream: layer-0 GEMM (needs g_x + dinvs) overlaps k_fill
    cudaStreamWaitEvent(s2, ev_mid, 0);
    k_gemm_mma<<<GEMM_GRID, T, GSMEM, s2>>>(nullptr, nullptr, NN, 1, 1);
    cudaEventRecord(ev_join, s2);

    // main stream: CSR fill
    k_fill<<<(EE + T - 1) / T, T>>>(src, dst);

    // join before layer loop
    cudaStreamWaitEvent(0, ev_join, 0);

    for (int i = 0; i < LLAY; i++) {
        if (i > 0)
            k_gemm_mma<<<GEMM_GRID, T, GSMEM>>>(nullptr, nullptr, NN, 1, i + 1);
        k_aggln<<<(NN * 32 + T - 1) / T, T>>>(gcn_b + i * HIDD,
                                              ln_g + i * HIDD, ln_b + i * HIDD,
                                              out, batch_idx,
                                              (i > 0) ? 1 : 0,
                                              (i == LLAY - 1) ? 1 : 0);
    }

    k_poolfin<<<(BB * HIDD + T - 1) / T, T>>>(out);
}